// round 5
// baseline (speedup 1.0000x reference)
#include <cuda_runtime.h>
#include <cstdint>

// Problem constants
#define BD   32
#define DDIM 256
#define HW   1024           // 32*32
#define NN   32768          // B*H*W rows
#define KK   1024           // codebook size
#define NZ   8388608        // B*D*H*W output elements of z_q
#define GATHER_BLOCKS 1024  // NN / 32

// Device scratch (no allocations allowed)
__device__ int   g_idx[NN];
__device__ float g_ek2[KK];
__device__ float g_zn2[NN];
__device__ float g_partial[GATHER_BLOCKS];

// ---------------- packed fp32x2 helpers ----------------
static __device__ __forceinline__ float2 unpack2(unsigned long long v) {
    float2 f;
    asm("mov.b64 {%0, %1}, %2;" : "=f"(f.x), "=f"(f.y) : "l"(v));
    return f;
}
static __device__ __forceinline__ void fma2(unsigned long long &d,
                                            unsigned long long a,
                                            unsigned long long b) {
    asm("fma.rn.f32x2 %0, %1, %2, %0;" : "+l"(d) : "l"(a), "l"(b));
}

// ---------------- cp.async helpers ----------------
static __device__ __forceinline__ void cp16(void* smem_dst, const void* gsrc) {
    unsigned s = (unsigned)__cvta_generic_to_shared(smem_dst);
    asm volatile("cp.async.cg.shared.global [%0], [%1], 16;" :: "r"(s), "l"(gsrc));
}
static __device__ __forceinline__ void cp_commit() {
    asm volatile("cp.async.commit_group;");
}
template <int N>
static __device__ __forceinline__ void cp_wait() {
    asm volatile("cp.async.wait_group %0;" :: "n"(N));
}

// ---------------- kernel A: ||e_k||^2 ----------------
__global__ void ek2_kernel(const float* __restrict__ emb) {
    int k = blockIdx.x * 8 + (threadIdx.x >> 5);
    int lane = threadIdx.x & 31;
    const float* row = emb + (size_t)k * DDIM;
    float s = 0.f;
#pragma unroll
    for (int i = 0; i < 8; ++i) {
        float v = row[lane + 32 * i];
        s = fmaf(v, v, s);
    }
#pragma unroll
    for (int o = 16; o; o >>= 1) s += __shfl_down_sync(0xffffffffu, s, o);
    if (lane == 0) g_ek2[k] = s;
}

// ---------------- kernel A2: ||z_n||^2, XLA-CPU scalar reduce order ----------
__global__ void zn2_kernel(const float* __restrict__ z) {
    int n  = blockIdx.x * 256 + threadIdx.x;   // n = b*1024 + hw
    int b  = n >> 10;
    int hw = n & 1023;
    const float* p = z + (size_t)b * (DDIM * HW) + hw;
    float acc = 0.f;
#pragma unroll 8
    for (int d = 0; d < DDIM; ++d) {
        float v = p[(size_t)d * HW];
        acc = __fadd_rn(acc, __fmul_rn(v, v));
    }
    g_zn2[n] = acc;
}

// ---------------- kernel B: fused distance GEMM + argmin ----------------
// Thread (tx,ty): m in {4tx..4tx+3} u {4tx+64..4tx+67} (pairs in f32x2 lanes);
//                 k = ty + 16*j, j=0..7.
// dot = sequential fp32 fma chain over ascending d (bit-matching Eigen gebp).
// dist = fl( fl(zn2 + ek2) - 2*dot ); argmin, lowest-index tie-break.
__global__ void __launch_bounds__(256, 2)
vq_argmin_kernel(const float* __restrict__ z, const float* __restrict__ emb) {
    __shared__ __align__(16) float Zs[2][16][128];   // 16 KB, [dd][m]
    __shared__ __align__(16) float Es[2][128][16];   // 16 KB, [k][dd] staging
    __shared__ __align__(16) float Ed[128][32];      // 16 KB, [k][(e,e) per dd]
    __shared__ float ek2s[KK];                       // 4 KB
    __shared__ float zn2s[128];

    const int tid = threadIdx.x;
    const int tx  = tid & 15;
    const int ty  = tid >> 4;
    const int m0  = blockIdx.x * 128;
    const int b   = m0 >> 10;      // blocks never straddle a batch
    const int hw0 = m0 & 1023;
    const float* zb = z + (size_t)b * (DDIM * HW) + hw0;

#pragma unroll
    for (int r = 0; r < 4; ++r) ek2s[tid + 256 * r] = g_ek2[tid + 256 * r];
    if (tid < 128) zn2s[tid] = g_zn2[m0 + tid];

    float bestv[8];
    int   besti[8];
#pragma unroll
    for (int q = 0; q < 8; ++q) { bestv[q] = 3.4e38f; besti[q] = 0; }

#pragma unroll 1
    for (int kt = 0; kt < 8; ++kt) {
        const int k0 = kt * 128;

        unsigned long long acc[8][4];   // [j][pair]
#pragma unroll
        for (int j = 0; j < 8; ++j)
#pragma unroll
            for (int p = 0; p < 4; ++p) acc[j][p] = 0ull;

        auto loadTile = [&](int dc, int bufw) {
            const int d0 = dc * 16;
#pragma unroll
            for (int r = 0; r < 2; ++r) {               // Z: 512 float4
                int i4 = tid + 256 * r;
                int dd = i4 >> 5;
                int mq = (i4 & 31) << 2;
                cp16(&Zs[bufw][dd][mq], zb + (size_t)(d0 + dd) * HW + mq);
            }
#pragma unroll
            for (int r = 0; r < 2; ++r) {               // E: 512 float4, row-major
                int i = tid + 256 * r;
                int k = i >> 2;
                int q = (i & 3) << 2;
                cp16(&Es[bufw][k][q], emb + (size_t)(k0 + k) * DDIM + d0 + q);
            }
        };

        loadTile(0, 0);
        cp_commit();
        int buf = 0;
#pragma unroll 1
        for (int dc = 0; dc < 16; ++dc) {
            if (dc < 15) {
                loadTile(dc + 1, buf ^ 1);
                cp_commit();
                cp_wait<1>();
            } else {
                cp_wait<0>();
            }
            __syncthreads();

            // duplicate E tile: Ed[k][2*dd] = Ed[k][2*dd+1] = Es[k][dd]
            {
                const float* Esrc = &Es[buf][0][0];
#pragma unroll
                for (int r = 0; r < 8; ++r) {
                    int idx = tid + 256 * r;     // linear over [k][dd]
                    float e = Esrc[idx];
                    unsigned ad = (unsigned)__cvta_generic_to_shared(
                        &Ed[idx >> 4][(idx & 15) << 1]);
                    asm volatile("st.shared.v2.f32 [%0], {%1, %1};"
                                 :: "r"(ad), "f"(e));
                }
            }
            __syncthreads();

            const float (*Zc)[128] = Zs[buf];
#pragma unroll
            for (int ddp = 0; ddp < 8; ++ddp) {          // d ascending overall
                const int dd = 2 * ddp;
                ulonglong2 zA0 = *(const ulonglong2*)&Zc[dd][4 * tx];
                ulonglong2 zA1 = *(const ulonglong2*)&Zc[dd][4 * tx + 64];
                ulonglong2 zB0 = *(const ulonglong2*)&Zc[dd + 1][4 * tx];
                ulonglong2 zB1 = *(const ulonglong2*)&Zc[dd + 1][4 * tx + 64];
#pragma unroll
                for (int j = 0; j < 8; ++j) {
                    ulonglong2 ep = *(const ulonglong2*)&Ed[ty + 16 * j][dd << 1];
                    fma2(acc[j][0], zA0.x, ep.x);   // d = dd
                    fma2(acc[j][1], zA0.y, ep.x);
                    fma2(acc[j][2], zA1.x, ep.x);
                    fma2(acc[j][3], zA1.y, ep.x);
                    fma2(acc[j][0], zB0.x, ep.y);   // d = dd+1 (chain order kept)
                    fma2(acc[j][1], zB0.y, ep.y);
                    fma2(acc[j][2], zB1.x, ep.y);
                    fma2(acc[j][3], zB1.y, ep.y);
                }
            }
            __syncthreads();
            buf ^= 1;
        }

        // fold this k-tile: dist = fl( fl(zn2 + ek2) - 2*dot ), reference rounding
#pragma unroll
        for (int j = 0; j < 8; ++j) {
            const int kk = k0 + ty + 16 * j;
            const float e2 = ek2s[kk];
#pragma unroll
            for (int p = 0; p < 4; ++p) {
                const int mloc = 4 * tx + ((p & 1) << 1) + ((p >> 1) << 6);
                float2 a2 = unpack2(acc[j][p]);
                float t0 = __fadd_rn(zn2s[mloc], e2);
                float v0 = fmaf(-2.f, a2.x, t0);
                if (v0 < bestv[2 * p]) { bestv[2 * p] = v0; besti[2 * p] = kk; }
                float t1 = __fadd_rn(zn2s[mloc + 1], e2);
                float v1 = fmaf(-2.f, a2.y, t1);
                if (v1 < bestv[2 * p + 1]) { bestv[2 * p + 1] = v1; besti[2 * p + 1] = kk; }
            }
        }
    }

    // cross-ty reduction (reuse Zs/Es smem; all cp.async drained)
    float* Rv = &Zs[0][0][0];      // 16 x 128 floats
    int*   Ri = (int*)&Es[0][0][0];
    __syncthreads();
#pragma unroll
    for (int p = 0; p < 4; ++p) {
#pragma unroll
        for (int h = 0; h < 2; ++h) {
            int mloc = 4 * tx + ((p & 1) << 1) + ((p >> 1) << 6) + h;
            Rv[ty * 128 + mloc] = bestv[2 * p + h];
            Ri[ty * 128 + mloc] = besti[2 * p + h];
        }
    }
    __syncthreads();
    if (tid < 128) {
        float bv = Rv[tid];
        int   bi = Ri[tid];
#pragma unroll
        for (int t = 1; t < 16; ++t) {
            float v = Rv[t * 128 + tid];
            int   i = Ri[t * 128 + tid];
            if (v < bv || (v == bv && i < bi)) { bv = v; bi = i; }
        }
        g_idx[m0 + tid] = bi;
    }
}

// ---------------- kernel C: gather z_q (smem-staged, coalesced) -------------
__global__ void __launch_bounds__(256)
gather_kernel(const float* __restrict__ z, const float* __restrict__ emb,
              float* __restrict__ out) {
    __shared__ float rows[32][257];   // pad -> conflict-free transpose reads
    __shared__ int   idxs[32];
    __shared__ float red[256];

    const int tid = threadIdx.x;
    const int n0  = blockIdx.x * 32;
    const int b   = n0 >> 10;
    const int hw0 = n0 & 1023;

    if (tid < 32) idxs[tid] = g_idx[n0 + tid];
    __syncthreads();

    const int rbase = tid >> 6;          // 0..3
    const int c4    = (tid & 63) << 2;   // 0..252
#pragma unroll
    for (int rr = 0; rr < 8; ++rr) {
        int r = rbase + rr * 4;
        float4 v = *(const float4*)(emb + (size_t)idxs[r] * DDIM + c4);
        rows[r][c4]     = v.x;
        rows[r][c4 + 1] = v.y;
        rows[r][c4 + 2] = v.z;
        rows[r][c4 + 3] = v.w;
    }
    __syncthreads();

    const int j  = tid & 31;   // hw offset within block
    const int ds = tid >> 5;   // 8 d's per pass
    float s = 0.f;
    const float* zp = z   + (size_t)b * (DDIM * HW) + hw0 + j;
    float*       op = out + (size_t)b * (DDIM * HW) + hw0 + j;
#pragma unroll 8
    for (int pass = 0; pass < 32; ++pass) {
        int d = pass * 8 + ds;
        float q  = rows[j][d];
        size_t off = (size_t)d * HW;
        float zv = zp[off];
        float df = __fadd_rn(q, -zv);      // fl(z_q - z)
        op[off] = __fadd_rn(zv, df);       // straight-through fl(z + fl(z_q - z))
        s = fmaf(df, df, s);
    }

    red[tid] = s;
    __syncthreads();
#pragma unroll
    for (int o = 128; o; o >>= 1) {
        if (tid < o) red[tid] += red[tid + o];
        __syncthreads();
    }
    if (tid == 0) g_partial[blockIdx.x] = red[0];
}

// ---------------- kernel D: finalize loss (deterministic tree reduce) --------
__global__ void finalize_kernel(float* __restrict__ out) {
    __shared__ float red[256];
    float s = 0.f;
#pragma unroll
    for (int r = 0; r < GATHER_BLOCKS / 256; ++r)
        s += g_partial[threadIdx.x + 256 * r];
    red[threadIdx.x] = s;
    __syncthreads();
#pragma unroll
    for (int o = 128; o; o >>= 1) {
        if (threadIdx.x < o) red[threadIdx.x] += red[threadIdx.x + o];
        __syncthreads();
    }
    if (threadIdx.x == 0) {
        float q = red[0] / (float)NZ;          // /2^23 exact
        out[NZ] = __fadd_rn(q, 0.25f * q);     // loss = q_latent + 0.25*e_latent
    }
}

// ---------------- kernel E: indices as float ----------------
__global__ void idx_out_kernel(float* __restrict__ out) {
    int n = blockIdx.x * 256 + threadIdx.x;
    out[NZ + 1 + n] = (float)g_idx[n];
}

extern "C" void kernel_launch(void* const* d_in, const int* in_sizes, int n_in,
                              void* d_out, int out_size) {
    const float* a0 = (const float*)d_in[0];
    const float* a1 = (const float*)d_in[1];
    const float* z;
    const float* emb;
    if (in_sizes[0] == NZ) { z = a0; emb = a1; }
    else                   { z = a1; emb = a0; }
    float* out = (float*)d_out;

    ek2_kernel<<<128, 256>>>(emb);
    zn2_kernel<<<NN / 256, 256>>>(z);
    vq_argmin_kernel<<<256, 256>>>(z, emb);
    gather_kernel<<<GATHER_BLOCKS, 256>>>(z, emb, out);
    if (out_size > NZ)            finalize_kernel<<<1, 256>>>(out);
    if (out_size >= NZ + 1 + NN)  idx_out_kernel<<<NN / 256, 256>>>(out);
}

// round 6
// speedup vs baseline: 1.2153x; 1.2153x over previous
#include <cuda_runtime.h>
#include <cuda_fp16.h>
#include <cstdint>

// Problem constants
#define DDIM 256
#define HW   1024
#define NN   32768
#define KK   1024
#define NZ   8388608
#define KC   768            // concatenated split-K (3 x 256)
#define GATHER_BLOCKS 1024
#define MAXC 16
#define MARGIN 2e-4f
#define ESCALE 1024.0f      // e pre-scale so e_lo stays fp16-normal
#define INV2ESCALE (-2.0f / 1024.0f)

// Device scratch (static — no allocations)
__device__ int    g_idx[NN];
__device__ float  g_ek2[KK];
__device__ float  g_zn2[NN];
__device__ float  g_partial[GATHER_BLOCKS];
__device__ __half g_zcat[(size_t)NN * KC];     // [n][ z_hi | z_hi | z_lo ]
__device__ __half g_ecat[(size_t)KK * KC];     // [k][ e_hi | e_lo | e_hi ] (scaled)
__device__ float  g_dist[(size_t)NN * KK];     // approx distances
__device__ int    g_cand[NN][MAXC];
__device__ int    g_ccnt[NN];

// ---------------- cp.async helpers ----------------
static __device__ __forceinline__ void cp16(void* smem_dst, const void* gsrc) {
    unsigned s = (unsigned)__cvta_generic_to_shared(smem_dst);
    asm volatile("cp.async.cg.shared.global [%0], [%1], 16;" :: "r"(s), "l"(gsrc));
}
static __device__ __forceinline__ void cp_commit() {
    asm volatile("cp.async.commit_group;");
}
template <int N>
static __device__ __forceinline__ void cp_wait() {
    asm volatile("cp.async.wait_group %0;" :: "n"(N));
}

// ---------------- mma helpers ----------------
static __device__ __forceinline__ unsigned sptr(const void* p) {
    return (unsigned)__cvta_generic_to_shared(p);
}
static __device__ __forceinline__ void ldsm4(unsigned& r0, unsigned& r1,
                                             unsigned& r2, unsigned& r3, unsigned a) {
    asm volatile("ldmatrix.sync.aligned.m8n8.x4.shared.b16 {%0,%1,%2,%3}, [%4];"
                 : "=r"(r0), "=r"(r1), "=r"(r2), "=r"(r3) : "r"(a));
}
static __device__ __forceinline__ void mma16816(float* c, const unsigned* a,
                                                const unsigned* b) {
    asm volatile(
        "mma.sync.aligned.m16n8k16.row.col.f32.f16.f16.f32 "
        "{%0,%1,%2,%3}, {%4,%5,%6,%7}, {%8,%9}, {%0,%1,%2,%3};"
        : "+f"(c[0]), "+f"(c[1]), "+f"(c[2]), "+f"(c[3])
        : "r"(a[0]), "r"(a[1]), "r"(a[2]), "r"(a[3]), "r"(b[0]), "r"(b[1]));
}

// ---------------- kernel A: ||e_k||^2 (exact) ----------------
__global__ void ek2_kernel(const float* __restrict__ emb) {
    int k = blockIdx.x * 8 + (threadIdx.x >> 5);
    int lane = threadIdx.x & 31;
    const float* row = emb + (size_t)k * DDIM;
    float s = 0.f;
#pragma unroll
    for (int i = 0; i < 8; ++i) {
        float v = row[lane + 32 * i];
        s = fmaf(v, v, s);
    }
#pragma unroll
    for (int o = 16; o; o >>= 1) s += __shfl_down_sync(0xffffffffu, s, o);
    if (lane == 0) g_ek2[k] = s;
}

// ---------------- kernel A2: ||z_n||^2, XLA-CPU scalar reduce order ----------
__global__ void zn2_kernel(const float* __restrict__ z) {
    int n  = blockIdx.x * 256 + threadIdx.x;
    int b  = n >> 10;
    int hw = n & 1023;
    const float* p = z + (size_t)b * (DDIM * HW) + hw;
    float acc = 0.f;
#pragma unroll 8
    for (int d = 0; d < DDIM; ++d) {
        float v = p[(size_t)d * HW];
        acc = __fadd_rn(acc, __fmul_rn(v, v));
    }
    g_zn2[n] = acc;
}

// ---------------- split kernels (fp16 hi/lo) ----------------
__global__ void splitz_kernel(const float* __restrict__ z) {
    int n    = blockIdx.x * 8 + (threadIdx.x >> 5);
    int lane = threadIdx.x & 31;
    int b = n >> 10, hw = n & 1023;
    const float* zp = z + (size_t)b * (DDIM * HW) + hw;
    __half* A = g_zcat + (size_t)n * KC;
#pragma unroll
    for (int i = 0; i < 8; ++i) {
        int d = lane + 32 * i;
        float v = zp[(size_t)d * HW];
        __half h = __float2half_rn(v);
        __half l = __float2half_rn(v - __half2float(h));
        A[d] = h; A[256 + d] = h; A[512 + d] = l;
    }
}
__global__ void splite_kernel(const float* __restrict__ emb) {
    int k = blockIdx.x;
    int d = threadIdx.x;
    float v = emb[(size_t)k * DDIM + d] * ESCALE;
    __half h = __float2half_rn(v);
    __half l = __float2half_rn(v - __half2float(h));
    __half* B = g_ecat + (size_t)k * KC;
    B[d] = h; B[256 + d] = l; B[512 + d] = h;
}

// ---------------- kernel G: fp16 MMA GEMM -> approx distances ---------------
// CTA: 128m x 128n, K-stage 32, double buffered. 8 warps = 2(m) x 4(n),
// warp tile 64m x 32n. smem rows: 32 halves (64B), 16B-granule XOR swizzle.
__global__ void __launch_bounds__(256, 2)
vq_gemm_kernel() {
    __shared__ __align__(16) __half As[2][128][32];
    __shared__ __align__(16) __half Bs[2][128][32];

    const int tid  = threadIdx.x;
    const int w    = tid >> 5;
    const int lane = tid & 31;
    const int wm   = (w & 1) * 64;
    const int wn   = (w >> 1) * 32;
    const int m0   = blockIdx.x * 128;
    const int n0   = blockIdx.y * 128;

    float c[4][4][4];
#pragma unroll
    for (int ms = 0; ms < 4; ++ms)
#pragma unroll
        for (int ns = 0; ns < 4; ++ns)
#pragma unroll
            for (int q = 0; q < 4; ++q) c[ms][ns][q] = 0.f;

    auto loadStage = [&](int kt, int buf) {
        const int kc0 = kt * 32;
#pragma unroll
        for (int r = 0; r < 2; ++r) {
            int i = tid + 256 * r;
            int row = i >> 2;
            int seg = i & 3;
            int sp  = (seg ^ (row & 3)) << 3;       // XOR-swizzled 16B granule
            cp16(&As[buf][row][sp],
                 g_zcat + (size_t)(m0 + row) * KC + kc0 + seg * 8);
            cp16(&Bs[buf][row][sp],
                 g_ecat + (size_t)(n0 + row) * KC + kc0 + seg * 8);
        }
    };

    loadStage(0, 0);
    cp_commit();
    int buf = 0;
#pragma unroll 1
    for (int kt = 0; kt < KC / 32; ++kt) {
        if (kt < KC / 32 - 1) {
            loadStage(kt + 1, buf ^ 1);
            cp_commit();
            cp_wait<1>();
        } else {
            cp_wait<0>();
        }
        __syncthreads();

#pragma unroll
        for (int kh = 0; kh < 2; ++kh) {
            unsigned a[4][4], b[4][2];
#pragma unroll
            for (int ms = 0; ms < 4; ++ms) {
                int row = wm + ms * 16 + (lane & 15);
                int seg = kh * 2 + (lane >> 4);
                ldsm4(a[ms][0], a[ms][1], a[ms][2], a[ms][3],
                      sptr(&As[buf][row][(seg ^ (row & 3)) << 3]));
            }
#pragma unroll
            for (int np = 0; np < 2; ++np) {
                int row = wn + np * 16 + (lane & 15);
                int seg = kh * 2 + (lane >> 4);
                unsigned r0, r1, r2, r3;
                ldsm4(r0, r1, r2, r3,
                      sptr(&Bs[buf][row][(seg ^ (row & 3)) << 3]));
                b[2 * np][0] = r0;     b[2 * np][1] = r2;
                b[2 * np + 1][0] = r1; b[2 * np + 1][1] = r3;
            }
#pragma unroll
            for (int ms = 0; ms < 4; ++ms)
#pragma unroll
                for (int ns = 0; ns < 4; ++ns)
                    mma16816(c[ms][ns], a[ms], b[ns]);
        }
        __syncthreads();
        buf ^= 1;
    }

    // epilogue: adist = ek2 - 2*dot  (dot scaled by ESCALE)
    const int gid = lane >> 2;
    const int tg  = lane & 3;
#pragma unroll
    for (int ms = 0; ms < 4; ++ms) {
#pragma unroll
        for (int ns = 0; ns < 4; ++ns) {
            int row = m0 + wm + ms * 16 + gid;
            int col = n0 + wn + ns * 8 + tg * 2;
            float e0 = g_ek2[col], e1 = g_ek2[col + 1];
            float2 v0 = make_float2(fmaf(INV2ESCALE, c[ms][ns][0], e0),
                                    fmaf(INV2ESCALE, c[ms][ns][1], e1));
            *(float2*)&g_dist[(size_t)row * KK + col] = v0;
            float2 v1 = make_float2(fmaf(INV2ESCALE, c[ms][ns][2], e0),
                                    fmaf(INV2ESCALE, c[ms][ns][3], e1));
            *(float2*)&g_dist[(size_t)(row + 8) * KK + col] = v1;
        }
    }
}

// ---------------- kernel S: per-row min + margin candidates -----------------
__global__ void scan_kernel() {
    __shared__ int scnt[8];
    int w    = threadIdx.x >> 5;
    int lane = threadIdx.x & 31;
    int n    = blockIdx.x * 8 + w;
    const float* dr = g_dist + (size_t)n * KK;

    float vals[32];
    float bv = 3.4e38f; int bi = 0;
#pragma unroll
    for (int i = 0; i < 32; ++i) {
        float v = dr[lane + 32 * i];
        vals[i] = v;
        if (v < bv) { bv = v; bi = lane + 32 * i; }   // ascending k: strict < keeps lowest
    }
#pragma unroll
    for (int o = 16; o; o >>= 1) {
        float ov = __shfl_xor_sync(0xffffffffu, bv, o);
        int   oi = __shfl_xor_sync(0xffffffffu, bi, o);
        if (ov < bv || (ov == bv && oi < bi)) { bv = ov; bi = oi; }
    }
    if (lane == 0) scnt[w] = 0;
    __syncwarp();
    float thr = bv + MARGIN;
#pragma unroll
    for (int i = 0; i < 32; ++i) {
        if (vals[i] <= thr) {
            int s = atomicAdd(&scnt[w], 1);
            if (s < MAXC) g_cand[n][s] = lane + 32 * i;
        }
    }
    __syncwarp();
    if (lane == 0) g_ccnt[n] = scnt[w];
}

// ---------------- kernel R: exact refine over candidates --------------------
// Exact sequential fp32 fma chain over ascending d (Eigen order), exact
// comparator fl(fl(zn2+ek2)-2*dot), lowest-index tie-break.
__global__ void refine_kernel(const float* __restrict__ z,
                              const float* __restrict__ emb) {
    int w    = threadIdx.x >> 5;
    int lane = threadIdx.x & 31;
    int n0   = blockIdx.x * 256 + w * 32;
    int n    = n0 + lane;
    int b    = n0 >> 10;
    int hw   = (n0 & 1023) + lane;

    int cnt  = g_ccnt[n];
    int full = (cnt > MAXC);
    int cl   = full ? 0 : cnt;
    int maxc = cl;
#pragma unroll
    for (int o = 16; o; o >>= 1)
        maxc = max(maxc, __shfl_xor_sync(0xffffffffu, maxc, o));

    const float* zp = z + (size_t)b * (DDIM * HW) + hw;
    const float  zn = g_zn2[n];
    float bv = 3.4e38f; int bi = 0;

    for (int s = 0; s < maxc; ++s) {
        int k = g_cand[n][(s < cl) ? s : 0];
        const float* ep = emb + (size_t)k * DDIM;
        float acc = 0.f;
#pragma unroll 8
        for (int d = 0; d < DDIM; ++d)
            acc = fmaf(zp[(size_t)d * HW], ep[d], acc);
        float dist = fmaf(-2.f, acc, __fadd_rn(zn, g_ek2[k]));
        if (s < cl && (dist < bv || (dist == bv && k < bi))) { bv = dist; bi = k; }
    }
    if (full) {   // correctness fallback (astronomically rare)
        bv = 3.4e38f; bi = 0;
        for (int k = 0; k < KK; ++k) {
            const float* ep = emb + (size_t)k * DDIM;
            float acc = 0.f;
#pragma unroll 8
            for (int d = 0; d < DDIM; ++d)
                acc = fmaf(zp[(size_t)d * HW], ep[d], acc);
            float dist = fmaf(-2.f, acc, __fadd_rn(zn, g_ek2[k]));
            if (dist < bv) { bv = dist; bi = k; }
        }
    }
    g_idx[n] = bi;
}

// ---------------- kernel C: gather z_q (smem-staged, coalesced) -------------
__global__ void __launch_bounds__(256)
gather_kernel(const float* __restrict__ z, const float* __restrict__ emb,
              float* __restrict__ out) {
    __shared__ float rows[32][257];
    __shared__ int   idxs[32];
    __shared__ float red[256];

    const int tid = threadIdx.x;
    const int n0  = blockIdx.x * 32;
    const int b   = n0 >> 10;
    const int hw0 = n0 & 1023;

    if (tid < 32) idxs[tid] = g_idx[n0 + tid];
    __syncthreads();

    const int rbase = tid >> 6;
    const int c4    = (tid & 63) << 2;
#pragma unroll
    for (int rr = 0; rr < 8; ++rr) {
        int r = rbase + rr * 4;
        float4 v = *(const float4*)(emb + (size_t)idxs[r] * DDIM + c4);
        rows[r][c4]     = v.x;
        rows[r][c4 + 1] = v.y;
        rows[r][c4 + 2] = v.z;
        rows[r][c4 + 3] = v.w;
    }
    __syncthreads();

    const int j  = tid & 31;
    const int ds = tid >> 5;
    float s = 0.f;
    const float* zp = z   + (size_t)b * (DDIM * HW) + hw0 + j;
    float*       op = out + (size_t)b * (DDIM * HW) + hw0 + j;
#pragma unroll 8
    for (int pass = 0; pass < 32; ++pass) {
        int d = pass * 8 + ds;
        float q  = rows[j][d];
        size_t off = (size_t)d * HW;
        float zv = zp[off];
        float df = __fadd_rn(q, -zv);
        op[off] = __fadd_rn(zv, df);
        s = fmaf(df, df, s);
    }

    red[tid] = s;
    __syncthreads();
#pragma unroll
    for (int o = 128; o; o >>= 1) {
        if (tid < o) red[tid] += red[tid + o];
        __syncthreads();
    }
    if (tid == 0) g_partial[blockIdx.x] = red[0];
}

// ---------------- kernel D: finalize loss ----------------
__global__ void finalize_kernel(float* __restrict__ out) {
    __shared__ float red[256];
    float s = 0.f;
#pragma unroll
    for (int r = 0; r < GATHER_BLOCKS / 256; ++r)
        s += g_partial[threadIdx.x + 256 * r];
    red[threadIdx.x] = s;
    __syncthreads();
#pragma unroll
    for (int o = 128; o; o >>= 1) {
        if (threadIdx.x < o) red[threadIdx.x] += red[threadIdx.x + o];
        __syncthreads();
    }
    if (threadIdx.x == 0) {
        float q = red[0] / (float)NZ;
        out[NZ] = __fadd_rn(q, 0.25f * q);
    }
}

// ---------------- kernel E: indices as float ----------------
__global__ void idx_out_kernel(float* __restrict__ out) {
    int n = blockIdx.x * 256 + threadIdx.x;
    out[NZ + 1 + n] = (float)g_idx[n];
}

extern "C" void kernel_launch(void* const* d_in, const int* in_sizes, int n_in,
                              void* d_out, int out_size) {
    const float* a0 = (const float*)d_in[0];
    const float* a1 = (const float*)d_in[1];
    const float* z;
    const float* emb;
    if (in_sizes[0] == NZ) { z = a0; emb = a1; }
    else                   { z = a1; emb = a0; }
    float* out = (float*)d_out;

    ek2_kernel<<<128, 256>>>(emb);
    zn2_kernel<<<NN / 256, 256>>>(z);
    splite_kernel<<<KK, 256>>>(emb);
    splitz_kernel<<<NN / 8, 256>>>(z);
    vq_gemm_kernel<<<dim3(256, 8), 256>>>();
    scan_kernel<<<NN / 8, 256>>>();
    refine_kernel<<<NN / 256, 256>>>(z, emb);
    gather_kernel<<<GATHER_BLOCKS, 256>>>(z, emb, out);
    if (out_size > NZ)            finalize_kernel<<<1, 256>>>(out);
    if (out_size >= NZ + 1 + NN)  idx_out_kernel<<<NN / 256, 256>>>(out);
}